// round 5
// baseline (speedup 1.0000x reference)
#include <cuda_runtime.h>
#include <cstdint>
#include <cstddef>

// out[M,N] = x[M,K] @ (w[K,N] + 2 * lora_a[K,16] @ lora_b[16,N])
#define M_DIM 8192
#define N_DIM 8192
#define K_DIM 2048
#define SCALE 2.0f

// Scratch (device globals — allocation-free per harness rules).
// g_xr: x, rna-rounded to tf32 bits, k-permuted within 8-groups, [M,K]
// g_wt: fused W' = w + 2*A@B, rounded, TRANSPOSED [N,K], k-permuted
__device__ __align__(16) float g_xr[(size_t)M_DIM * K_DIM];
__device__ __align__(16) float g_wt[(size_t)N_DIM * K_DIM];

__device__ __forceinline__ float rna_tf32(float x) {
    uint32_t u; asm("cvt.rna.tf32.f32 %0, %1;" : "=r"(u) : "f"(x));
    return __uint_as_float(u);
}

// k-permutation within each 8-group: logical c -> 8*(c/8) + 2*(c&3) + ((c>>2)&1)
// (logical pairs (c, c+4) physically adjacent; applied to BOTH operands, so
// dot products — and the GEMM — are unchanged)

// ---------------------------------------------------------------------------
// Kernel 1: x -> rounded + k-permuted. Each thread handles one 8-group.
// ---------------------------------------------------------------------------
__global__ __launch_bounds__(256) void prep_x(const float4* __restrict__ x,
                                              float4* __restrict__ xr) {
    size_t i = ((size_t)blockIdx.x * 256 + threadIdx.x) * 2;
    float4 v0 = x[i], v1 = x[i + 1];
    float4 o0, o1;
    o0.x = rna_tf32(v0.x); o0.y = rna_tf32(v1.x);
    o0.z = rna_tf32(v0.y); o0.w = rna_tf32(v1.y);
    o1.x = rna_tf32(v0.z); o1.y = rna_tf32(v1.z);
    o1.z = rna_tf32(v0.w); o1.w = rna_tf32(v1.w);
    xr[i] = o0; xr[i + 1] = o1;
}

// ---------------------------------------------------------------------------
// Kernel 2: g_wt[n][P(k)] = rna(w[k][n] + 2*(A@B)[k][n]); 32x32 smem transpose
// ---------------------------------------------------------------------------
__global__ __launch_bounds__(256) void fuse_w_t(const float* __restrict__ w,
                                                const float* __restrict__ la,
                                                const float* __restrict__ lb) {
    __shared__ float t[32][33];
    __shared__ float bs[16][32];
    const int n0 = blockIdx.x * 32, k0 = blockIdx.y * 32;
    const int tid = threadIdx.x;
    const int tx = tid & 31, ty = tid >> 5;
    {
        int i0 = tid;
        bs[i0 >> 5][i0 & 31] = lb[(size_t)(i0 >> 5) * N_DIM + n0 + (i0 & 31)];
        int i1 = tid + 256;
        bs[i1 >> 5][i1 & 31] = lb[(size_t)(i1 >> 5) * N_DIM + n0 + (i1 & 31)];
    }
    __syncthreads();
#pragma unroll
    for (int i = 0; i < 4; i++) {
        const int kl = ty + 8 * i;
        const int k = k0 + kl;
        const float* ar = la + (size_t)k * 16;
        float acc = 0.f;
#pragma unroll
        for (int r = 0; r < 16; r++) acc += ar[r] * bs[r][tx];
        t[kl][tx] = rna_tf32(w[(size_t)k * N_DIM + n0 + tx] + SCALE * acc);
    }
    __syncthreads();
    const int ptx_ = (tx & 24) + 2 * (tx & 3) + ((tx >> 2) & 1);  // P(tx)
#pragma unroll
    for (int i = 0; i < 4; i++) {
        const int nl = ty + 8 * i;
        g_wt[(size_t)(n0 + nl) * K_DIM + k0 + ptx_] = t[tx][nl];
    }
}

// ---------------------------------------------------------------------------
// Kernel 3: tf32 mma.sync GEMM. CTA 128x128 / 128 threads, warp tile 64x64,
//           Ktile 32, double-buffered cp.async, conflict-free LDS.64 frags,
//           fragment regs double-buffered across ks, cp.async spread into
//           the MMA stream (no post-sync LSU burst).
// ---------------------------------------------------------------------------
constexpr int STRIDE = 40;                 // 32 + 8 pad (floats)
constexpr int T_ST = 128 * STRIDE;         // one tile: 5120 floats (20 KB)
constexpr int STAGE = 2 * T_ST;            // A + B per stage (40 KB)
constexpr int SMEM_BYTES = 2 * STAGE * 4;  // 81920

__device__ __forceinline__ void lds64(uint32_t& a, uint32_t& b, uint32_t addr) {
    asm volatile("ld.shared.v2.b32 {%0,%1}, [%2];" : "=r"(a), "=r"(b) : "r"(addr));
}
__device__ __forceinline__ void mma8(float c[4], const uint32_t a[4], const uint32_t b[2]) {
    asm volatile(
        "mma.sync.aligned.m16n8k8.row.col.f32.tf32.tf32.f32 "
        "{%0,%1,%2,%3}, {%4,%5,%6,%7}, {%8,%9}, {%0,%1,%2,%3};\n"
        : "+f"(c[0]), "+f"(c[1]), "+f"(c[2]), "+f"(c[3])
        : "r"(a[0]), "r"(a[1]), "r"(a[2]), "r"(a[3]), "r"(b[0]), "r"(b[1]));
}

__global__ __launch_bounds__(128, 2) void gemm_tf32(const float* __restrict__ A,
                                                    const float* __restrict__ B,
                                                    float* __restrict__ C) {
    extern __shared__ float smem[];
    const int tid = threadIdx.x;
    const int lane = tid & 31;
    const int warp = tid >> 5;   // 0..3
    const int wm = warp >> 1;    // 2 warps along M (64 rows)
    const int wn = warp & 1;     // 2 warps along N (64 cols)
    const int grp = lane >> 2;   // 0..7
    const int tig = lane & 3;    // 0..3
    const int blockM = blockIdx.y * 128;
    const int blockN = blockIdx.x * 128;

    const uint32_t smem_u = (uint32_t)__cvta_generic_to_shared(smem);

    float acc[4][8][4];
#pragma unroll
    for (int i = 0; i < 4; i++)
#pragma unroll
        for (int j = 0; j < 8; j++)
#pragma unroll
            for (int l = 0; l < 4; l++) acc[i][j][l] = 0.f;

    // cp.async A-half / B-half of a stage (8 float4 each per thread)
    auto load_A = [&](int s, int k0) {
        const uint32_t base = smem_u + (uint32_t)(s * STAGE) * 4u;
#pragma unroll
        for (int i = 0; i < 8; i++) {
            const int idx = tid + i * 128;
            const int row = idx >> 3, ch = idx & 7;
            const float* g = A + (size_t)(blockM + row) * K_DIM + k0 + ch * 4;
            const uint32_t d = base + (uint32_t)(row * STRIDE + ch * 4) * 4u;
            asm volatile("cp.async.cg.shared.global [%0], [%1], 16;\n" ::"r"(d), "l"(g));
        }
    };
    auto load_B = [&](int s, int k0) {
        const uint32_t base = smem_u + (uint32_t)(s * STAGE + T_ST) * 4u;
#pragma unroll
        for (int i = 0; i < 8; i++) {
            const int idx = tid + i * 128;
            const int row = idx >> 3, ch = idx & 7;
            const float* g = B + (size_t)(blockN + row) * K_DIM + k0 + ch * 4;
            const uint32_t d = base + (uint32_t)(row * STRIDE + ch * 4) * 4u;
            asm volatile("cp.async.cg.shared.global [%0], [%1], 16;\n" ::"r"(d), "l"(g));
        }
    };

    load_A(0, 0);
    load_B(0, 0);
    asm volatile("cp.async.commit_group;\n" ::: "memory");

    // double-buffered fragment registers (indexed by compile-time ks&1)
    uint32_t af[2][4][4], bf[2][8][2];

    const int KTILES = K_DIM / 32;  // 64
    for (int kt = 0; kt < KTILES; kt++) {
        asm volatile("cp.async.wait_group 0;\n" ::: "memory");
        __syncthreads();

        const uint32_t aTh = smem_u +
            (uint32_t)((kt & 1) * STAGE + (wm * 64 + grp) * STRIDE + 2 * tig) * 4u;
        const uint32_t bTh = smem_u +
            (uint32_t)((kt & 1) * STAGE + T_ST + (wn * 64 + grp) * STRIDE + 2 * tig) * 4u;

        // preload ks=0 fragments into buffer 0
#pragma unroll
        for (int mi = 0; mi < 4; mi++) {
            const uint32_t ap = aTh + (uint32_t)(mi * 16 * STRIDE) * 4u;
            lds64(af[0][mi][0], af[0][mi][2], ap);
            lds64(af[0][mi][1], af[0][mi][3], ap + (uint32_t)(8 * STRIDE) * 4u);
        }
#pragma unroll
        for (int ni = 0; ni < 8; ni++)
            lds64(bf[0][ni][0], bf[0][ni][1], bTh + (uint32_t)(ni * 8 * STRIDE) * 4u);

        const bool more = (kt + 1 < KTILES);
#pragma unroll
        for (int ks = 0; ks < 4; ks++) {
            const int cur = ks & 1, nxt = cur ^ 1;
            // prefetch next ks fragments (hidden under this ks's 32 MMAs)
            if (ks < 3) {
                const uint32_t ko = (uint32_t)((ks + 1) * 8) * 4u;
#pragma unroll
                for (int mi = 0; mi < 4; mi++) {
                    const uint32_t ap = aTh + (uint32_t)(mi * 16 * STRIDE) * 4u + ko;
                    lds64(af[nxt][mi][0], af[nxt][mi][2], ap);
                    lds64(af[nxt][mi][1], af[nxt][mi][3], ap + (uint32_t)(8 * STRIDE) * 4u);
                }
#pragma unroll
                for (int ni = 0; ni < 8; ni++)
                    lds64(bf[nxt][ni][0], bf[nxt][ni][1],
                          bTh + (uint32_t)(ni * 8 * STRIDE) * 4u + ko);
            }
            // spread the global prefetch into the MMA stream
            if (ks == 0 && more) load_A((kt + 1) & 1, (kt + 1) * 32);
            if (ks == 1 && more) {
                load_B((kt + 1) & 1, (kt + 1) * 32);
                asm volatile("cp.async.commit_group;\n" ::: "memory");
            }
#pragma unroll
            for (int mi = 0; mi < 4; mi++)
#pragma unroll
                for (int ni = 0; ni < 8; ni++)
                    mma8(acc[mi][ni], af[cur][mi], bf[cur][ni]);
        }
    }

    // Epilogue: c0/c1 at (row, 2*tig[+1]); c2/c3 at (row+8, ...)
#pragma unroll
    for (int mi = 0; mi < 4; mi++) {
        const int r0 = blockM + wm * 64 + mi * 16 + grp;
#pragma unroll
        for (int ni = 0; ni < 8; ni++) {
            const int c0 = blockN + wn * 64 + ni * 8 + 2 * tig;
            float2 v0 = make_float2(acc[mi][ni][0], acc[mi][ni][1]);
            float2 v1 = make_float2(acc[mi][ni][2], acc[mi][ni][3]);
            *reinterpret_cast<float2*>(C + (size_t)r0 * N_DIM + c0) = v0;
            *reinterpret_cast<float2*>(C + (size_t)(r0 + 8) * N_DIM + c0) = v1;
        }
    }
}

// ---------------------------------------------------------------------------
extern "C" void kernel_launch(void* const* d_in, const int* in_sizes, int n_in,
                              void* d_out, int out_size) {
    const float* x  = (const float*)d_in[0];  // [8192,2048]
    const float* w  = (const float*)d_in[1];  // [2048,8192]
    const float* la = (const float*)d_in[2];  // [2048,16]
    const float* lb = (const float*)d_in[3];  // [16,8192]
    float* out = (float*)d_out;               // [8192,8192]

    void *xr_p = nullptr, *wt_p = nullptr;
    cudaGetSymbolAddress(&xr_p, g_xr);
    cudaGetSymbolAddress(&wt_p, g_wt);

    prep_x<<<(int)(((size_t)M_DIM * K_DIM / 8) / 256), 256>>>(
        (const float4*)x, (float4*)xr_p);
    fuse_w_t<<<dim3(N_DIM / 32, K_DIM / 32), 256>>>(w, la, lb);

    cudaFuncSetAttribute(gemm_tf32, cudaFuncAttributeMaxDynamicSharedMemorySize, SMEM_BYTES);
    gemm_tf32<<<dim3(N_DIM / 128, M_DIM / 128), 128, SMEM_BYTES>>>(
        (const float*)xr_p, (const float*)wt_p, out);
}

// round 6
// speedup vs baseline: 2.1747x; 2.1747x over previous
#include <cuda_runtime.h>
#include <cuda_fp16.h>
#include <cstdint>
#include <cstddef>

// out[M,N] = x[M,K] @ (w[K,N] + 2 * lora_a[K,16] @ lora_b[16,N])
#define M_DIM 8192
#define N_DIM 8192
#define K_DIM 2048
#define SCALE 2.0f

// Scratch (device globals — allocation-free per harness rules).
// g_xh: x -> fp16 (rn), k-permuted within 16-groups, [M,K]
// g_wh: fused W' = w + 2*A@B -> fp16, TRANSPOSED [N,K], k-permuted
__device__ __align__(16) __half g_xh[(size_t)M_DIM * K_DIM];
__device__ __align__(16) __half g_wh[(size_t)N_DIM * K_DIM];

// k-permutation Q within each 16-group:
// logical {2t,2t+1,2t+8,2t+9} -> phys {4t..4t+3}  (t = 0..3)
// Applied to BOTH operands, so dot products (and the GEMM) are unchanged.
// Makes every m16n8k16 fragment k-quad physically contiguous (one LDS.64).

// ---------------------------------------------------------------------------
// Kernel 1: x -> fp16 + Q-permute. One thread = one 16-group (4 float4 in,
// 2 uint4 out).
// ---------------------------------------------------------------------------
__global__ __launch_bounds__(256) void prep_x(const float4* __restrict__ x,
                                              uint4* __restrict__ xh) {
    const size_t i = (size_t)blockIdx.x * 256 + threadIdx.x;  // 16-group index
    const float4 v0 = x[i * 4 + 0];   // l0..3
    const float4 v1 = x[i * 4 + 1];   // l4..7
    const float4 v2 = x[i * 4 + 2];   // l8..11
    const float4 v3 = x[i * 4 + 3];   // l12..15
    __half2 h[8];
    h[0] = __floats2half2_rn(v0.x, v0.y);  // l0,l1
    h[1] = __floats2half2_rn(v2.x, v2.y);  // l8,l9
    h[2] = __floats2half2_rn(v0.z, v0.w);  // l2,l3
    h[3] = __floats2half2_rn(v2.z, v2.w);  // l10,l11
    h[4] = __floats2half2_rn(v1.x, v1.y);  // l4,l5
    h[5] = __floats2half2_rn(v3.x, v3.y);  // l12,l13
    h[6] = __floats2half2_rn(v1.z, v1.w);  // l6,l7
    h[7] = __floats2half2_rn(v3.z, v3.w);  // l14,l15
    const uint4* u = reinterpret_cast<const uint4*>(h);
    xh[i * 2 + 0] = u[0];
    xh[i * 2 + 1] = u[1];
}

// ---------------------------------------------------------------------------
// Kernel 2: g_wh[n][Q(k)] = fp16(w[k][n] + 2*(A@B)[k][n]); 32x32 transpose
// ---------------------------------------------------------------------------
__global__ __launch_bounds__(256) void fuse_w_t(const float* __restrict__ w,
                                                const float* __restrict__ la,
                                                const float* __restrict__ lb) {
    __shared__ float t[32][33];
    __shared__ float bs[16][32];
    const int n0 = blockIdx.x * 32, k0 = blockIdx.y * 32;
    const int tid = threadIdx.x;
    const int tx = tid & 31, ty = tid >> 5;
    {
        int i0 = tid;
        bs[i0 >> 5][i0 & 31] = lb[(size_t)(i0 >> 5) * N_DIM + n0 + (i0 & 31)];
        int i1 = tid + 256;
        bs[i1 >> 5][i1 & 31] = lb[(size_t)(i1 >> 5) * N_DIM + n0 + (i1 & 31)];
    }
    __syncthreads();
#pragma unroll
    for (int i = 0; i < 4; i++) {
        const int kl = ty + 8 * i;
        const int k = k0 + kl;
        const float* ar = la + (size_t)k * 16;
        float acc = 0.f;
#pragma unroll
        for (int r = 0; r < 16; r++) acc += ar[r] * bs[r][tx];
        t[kl][tx] = w[(size_t)k * N_DIM + n0 + tx] + SCALE * acc;
    }
    __syncthreads();
    // Q(k) within 16-group: 4*((k>>1)&3) + (k&1) + 2*((k>>3)&1)
    const int wi = tx & 15;
    const int qk = (tx & 16) + 4 * ((wi >> 1) & 3) + (wi & 1) + 2 * ((wi >> 3) & 1);
#pragma unroll
    for (int i = 0; i < 4; i++) {
        const int nl = ty + 8 * i;
        g_wh[(size_t)(n0 + nl) * K_DIM + k0 + qk] = __float2half_rn(t[tx][nl]);
    }
}

// ---------------------------------------------------------------------------
// Kernel 3: fp16 mma.sync GEMM (f32 accum). CTA 128x128 / 128 threads,
//           warp tile 64x64, KTILE 64, 2-stage cp.async, LDS.64 fragments.
// ---------------------------------------------------------------------------
constexpr int KTILE = 64;                   // halves per k-tile
constexpr int STRIDE = 80;                  // 64 + 16 pad (halves); banks 8g+2t OK
constexpr int T_ST = 128 * STRIDE;          // one tile: 10240 halves (20 KB)
constexpr int STAGE = 2 * T_ST;             // A + B per stage (40 KB)
constexpr int SMEM_BYTES = 2 * STAGE * 2;   // 81920 B

__device__ __forceinline__ void lds64(uint32_t& a, uint32_t& b, uint32_t addr) {
    asm volatile("ld.shared.v2.b32 {%0,%1}, [%2];" : "=r"(a), "=r"(b) : "r"(addr));
}
__device__ __forceinline__ void mma16(float c[4], const uint32_t a[4], const uint32_t b[2]) {
    asm volatile(
        "mma.sync.aligned.m16n8k16.row.col.f32.f16.f16.f32 "
        "{%0,%1,%2,%3}, {%4,%5,%6,%7}, {%8,%9}, {%0,%1,%2,%3};\n"
        : "+f"(c[0]), "+f"(c[1]), "+f"(c[2]), "+f"(c[3])
        : "r"(a[0]), "r"(a[1]), "r"(a[2]), "r"(a[3]), "r"(b[0]), "r"(b[1]));
}

__global__ __launch_bounds__(128, 2) void gemm_f16(const __half* __restrict__ A,
                                                   const __half* __restrict__ B,
                                                   float* __restrict__ C) {
    extern __shared__ __half smem[];
    const int tid = threadIdx.x;
    const int lane = tid & 31;
    const int warp = tid >> 5;   // 0..3
    const int wm = warp >> 1;    // 2 warps along M (64 rows)
    const int wn = warp & 1;     // 2 warps along N (64 cols)
    const int grp = lane >> 2;   // 0..7
    const int tig = lane & 3;    // 0..3
    const int blockM = blockIdx.y * 128;
    const int blockN = blockIdx.x * 128;

    const uint32_t smem_u = (uint32_t)__cvta_generic_to_shared(smem);

    float acc[4][8][4];
#pragma unroll
    for (int i = 0; i < 4; i++)
#pragma unroll
        for (int j = 0; j < 8; j++)
#pragma unroll
            for (int l = 0; l < 4; l++) acc[i][j][l] = 0.f;

    // cp.async: each tile = 128 rows x 8 chunks of 16B (= 64 halves of data)
    auto load_stage = [&](int s, int k0) {
        const uint32_t baseA = smem_u + (uint32_t)(s * STAGE) * 2u;
        const uint32_t baseB = baseA + (uint32_t)T_ST * 2u;
#pragma unroll
        for (int i = 0; i < 8; i++) {
            const int idx = tid + i * 128;
            const int row = idx >> 3, ch = idx & 7;
            const __half* g = A + (size_t)(blockM + row) * K_DIM + k0 + ch * 8;
            const uint32_t d = baseA + (uint32_t)(row * STRIDE + ch * 8) * 2u;
            asm volatile("cp.async.cg.shared.global [%0], [%1], 16;\n" ::"r"(d), "l"(g));
        }
#pragma unroll
        for (int i = 0; i < 8; i++) {
            const int idx = tid + i * 128;
            const int row = idx >> 3, ch = idx & 7;
            const __half* g = B + (size_t)(blockN + row) * K_DIM + k0 + ch * 8;
            const uint32_t d = baseB + (uint32_t)(row * STRIDE + ch * 8) * 2u;
            asm volatile("cp.async.cg.shared.global [%0], [%1], 16;\n" ::"r"(d), "l"(g));
        }
    };

    load_stage(0, 0);
    asm volatile("cp.async.commit_group;\n" ::: "memory");

    const int KTILES = K_DIM / KTILE;  // 32
    for (int kt = 0; kt < KTILES; kt++) {
        asm volatile("cp.async.wait_group 0;\n" ::: "memory");
        __syncthreads();
        if (kt + 1 < KTILES) load_stage((kt + 1) & 1, (kt + 1) * KTILE);
        asm volatile("cp.async.commit_group;\n" ::: "memory");

        // per-thread fragment bases (bytes); frag quad at halves 16*ks + 4*tig
        const uint32_t aTh = smem_u +
            (uint32_t)((kt & 1) * STAGE + (wm * 64 + grp) * STRIDE + 4 * tig) * 2u;
        const uint32_t bTh = smem_u +
            (uint32_t)((kt & 1) * STAGE + T_ST + (wn * 64 + grp) * STRIDE + 4 * tig) * 2u;
#pragma unroll
        for (int ks = 0; ks < 4; ks++) {          // 4 x k16 per KTILE=64
            const uint32_t ko = (uint32_t)(ks * 16) * 2u;
            uint32_t af[4][4], bf[8][2];
#pragma unroll
            for (int mi = 0; mi < 4; mi++) {
                const uint32_t ap = aTh + (uint32_t)(mi * 16 * STRIDE) * 2u + ko;
                lds64(af[mi][0], af[mi][2], ap);                               // row grp
                lds64(af[mi][1], af[mi][3], ap + (uint32_t)(8 * STRIDE) * 2u); // row grp+8
            }
#pragma unroll
            for (int ni = 0; ni < 8; ni++) {
                const uint32_t bp = bTh + (uint32_t)(ni * 8 * STRIDE) * 2u + ko;
                lds64(bf[ni][0], bf[ni][1], bp);
            }
#pragma unroll
            for (int mi = 0; mi < 4; mi++)
#pragma unroll
                for (int ni = 0; ni < 8; ni++)
                    mma16(acc[mi][ni], af[mi], bf[ni]);
        }
    }

    // Epilogue: c0/c1 at (row, 2*tig[+1]); c2/c3 at (row+8, ...)
#pragma unroll
    for (int mi = 0; mi < 4; mi++) {
        const int r0 = blockM + wm * 64 + mi * 16 + grp;
#pragma unroll
        for (int ni = 0; ni < 8; ni++) {
            const int c0 = blockN + wn * 64 + ni * 8 + 2 * tig;
            float2 v0 = make_float2(acc[mi][ni][0], acc[mi][ni][1]);
            float2 v1 = make_float2(acc[mi][ni][2], acc[mi][ni][3]);
            *reinterpret_cast<float2*>(C + (size_t)r0 * N_DIM + c0) = v0;
            *reinterpret_cast<float2*>(C + (size_t)(r0 + 8) * N_DIM + c0) = v1;
        }
    }
}

// ---------------------------------------------------------------------------
extern "C" void kernel_launch(void* const* d_in, const int* in_sizes, int n_in,
                              void* d_out, int out_size) {
    const float* x  = (const float*)d_in[0];  // [8192,2048]
    const float* w  = (const float*)d_in[1];  // [2048,8192]
    const float* la = (const float*)d_in[2];  // [2048,16]
    const float* lb = (const float*)d_in[3];  // [16,8192]
    float* out = (float*)d_out;               // [8192,8192]

    void *xh_p = nullptr, *wh_p = nullptr;
    cudaGetSymbolAddress(&xh_p, g_xh);
    cudaGetSymbolAddress(&wh_p, g_wh);

    prep_x<<<(int)(((size_t)M_DIM * K_DIM / 16) / 256), 256>>>(
        (const float4*)x, (uint4*)xh_p);
    fuse_w_t<<<dim3(N_DIM / 32, K_DIM / 32), 256>>>(w, la, lb);

    cudaFuncSetAttribute(gemm_f16, cudaFuncAttributeMaxDynamicSharedMemorySize, SMEM_BYTES);
    gemm_f16<<<dim3(N_DIM / 128, M_DIM / 128), 128, SMEM_BYTES>>>(
        (const __half*)xh_p, (const __half*)wh_p, out);
}